// round 6
// baseline (speedup 1.0000x reference)
#include <cuda_runtime.h>
#include <cstdint>
#include <cstddef>

// CriticRNN: T=128, NE=64, NA=8, OBS=64, D=128, CH=128, VH=256, ITERS=2, B=512
// Round 6: 3 launches. embed_gi (MT=2, 2 CTA/SM) -> gru -> post-GRU megakernel
// (all of couple/delta/value fused per 64-row block; intermediates smem-only).

#define TBROWS 65536
typedef unsigned long long ull;

__device__ float g_gi[(size_t)TBROWS * 384];
__device__ float g_e [(size_t)TBROWS * 128];

__device__ __forceinline__ uint32_t f2tf32(float x) {
    uint32_t u; asm("cvt.rna.tf32.f32 %0, %1;" : "=r"(u) : "f"(x)); return u;
}
__device__ __forceinline__ ull pack2(float lo, float hi) {
    ull r; asm("mov.b64 %0, {%1, %2};" : "=l"(r) : "f"(lo), "f"(hi)); return r;
}
__device__ __forceinline__ void unpack2(ull v, float& a, float& b) {
    asm("mov.b64 {%0, %1}, %2;" : "=f"(a), "=f"(b) : "l"(v));
}
__device__ __forceinline__ ull fma2(ull a, ull b, ull c) {
    ull d; asm("fma.rn.f32x2 %0, %1, %2, %3;" : "=l"(d) : "l"(a), "l"(b), "l"(c));
    return d;
}
__device__ __forceinline__ void mma8(float c[4],
    uint32_t a0, uint32_t a1, uint32_t a2, uint32_t a3, uint32_t b0, uint32_t b1)
{
    asm volatile(
        "mma.sync.aligned.m16n8k8.row.col.f32.tf32.tf32.f32 "
        "{%0,%1,%2,%3},{%4,%5,%6,%7},{%8,%9},{%0,%1,%2,%3};"
        : "+f"(c[0]), "+f"(c[1]), "+f"(c[2]), "+f"(c[3])
        : "r"(a0), "r"(a1), "r"(a2), "r"(a3), "r"(b0), "r"(b1));
}

// ======== GEMM building blocks. Block tile (MT*32) x 128, 8 warps (2m x 4n),
// ======== warp tile (MT*16) x 32, k-chunk 32. All smem strides ≡ 4 (mod 32).

template<int MT>
__device__ __forceinline__ void acc_zero(float (&acc)[MT][4][4]) {
#pragma unroll
    for (int mt = 0; mt < MT; mt++)
#pragma unroll
        for (int nt = 0; nt < 4; nt++)
#pragma unroll
            for (int q = 0; q < 4; q++) acc[mt][nt][q] = 0.f;
}

template<int MT>
__device__ __forceinline__ void compute_chunk(
    const uint32_t* __restrict__ asrc, int astr, const uint32_t* __restrict__ Bs,
    float (&acc)[MT][4][4], int wm0, int wn0, int g, int t4)
{
#pragma unroll
    for (int ks = 0; ks < 4; ks++) {
        const int kc = ks * 8 + t4;
        uint32_t af[MT][4], bf[4][2];
#pragma unroll
        for (int mt = 0; mt < MT; mt++) {
            const int r = wm0 + mt * 16 + g;
            af[mt][0] = asrc[r * astr + kc];
            af[mt][1] = asrc[(r + 8) * astr + kc];
            af[mt][2] = asrc[r * astr + kc + 4];
            af[mt][3] = asrc[(r + 8) * astr + kc + 4];
        }
#pragma unroll
        for (int nt = 0; nt < 4; nt++) {
            const int c = wn0 + nt * 8 + g;
            bf[nt][0] = Bs[kc * 136 + c];
            bf[nt][1] = Bs[(kc + 4) * 136 + c];
        }
#pragma unroll
        for (int mt = 0; mt < MT; mt++)
#pragma unroll
            for (int nt = 0; nt < 4; nt++)
                mma8(acc[mt][nt], af[mt][0], af[mt][1], af[mt][2], af[mt][3],
                     bf[nt][0], bf[nt][1]);
    }
}

// A streamed from gmem (fp32). A = block-row base. K multiple of 32.
template<int MT>
__device__ __forceinline__ void gemm_gmemA(
    const float* __restrict__ A, int lda, int K,
    const float* __restrict__ B, int ldb,
    uint32_t* As, uint32_t* Bs, float (&acc)[MT][4][4],
    int tid, int wm0, int wn0, int g, int t4)
{
    acc_zero<MT>(acc);
    float4 pa[MT], pb[4];
    const int nch = K >> 5;
    __syncthreads();
#pragma unroll
    for (int i = 0; i < MT; i++) {
        const int f = i * 256 + tid; const int r = f >> 3, c = (f & 7) << 2;
        pa[i] = *(const float4*)(A + (size_t)r * lda + c);
    }
#pragma unroll
    for (int i = 0; i < 4; i++) {
        const int f = i * 256 + tid; const int r = f >> 5, c = (f & 31) << 2;
        pb[i] = *(const float4*)(B + (size_t)r * ldb + c);
    }
#pragma unroll
    for (int i = 0; i < MT; i++) {
        const int f = i * 256 + tid; const int r = f >> 3, c = (f & 7) << 2;
        uint4 v; v.x = f2tf32(pa[i].x); v.y = f2tf32(pa[i].y);
        v.z = f2tf32(pa[i].z); v.w = f2tf32(pa[i].w);
        *(uint4*)&As[r * 36 + c] = v;
    }
#pragma unroll
    for (int i = 0; i < 4; i++) {
        const int f = i * 256 + tid; const int r = f >> 5, c = (f & 31) << 2;
        uint4 v; v.x = f2tf32(pb[i].x); v.y = f2tf32(pb[i].y);
        v.z = f2tf32(pb[i].z); v.w = f2tf32(pb[i].w);
        *(uint4*)&Bs[r * 136 + c] = v;
    }
    __syncthreads();
    for (int ch = 1; ch < nch; ch++) {
        const int k0 = ch * 32;
#pragma unroll
        for (int i = 0; i < MT; i++) {
            const int f = i * 256 + tid; const int r = f >> 3, c = (f & 7) << 2;
            pa[i] = *(const float4*)(A + (size_t)r * lda + k0 + c);
        }
#pragma unroll
        for (int i = 0; i < 4; i++) {
            const int f = i * 256 + tid; const int r = f >> 5, c = (f & 31) << 2;
            pb[i] = *(const float4*)(B + (size_t)(k0 + r) * ldb + c);
        }
        compute_chunk<MT>(As, 36, Bs, acc, wm0, wn0, g, t4);
        __syncthreads();
#pragma unroll
        for (int i = 0; i < MT; i++) {
            const int f = i * 256 + tid; const int r = f >> 3, c = (f & 7) << 2;
            uint4 v; v.x = f2tf32(pa[i].x); v.y = f2tf32(pa[i].y);
            v.z = f2tf32(pa[i].z); v.w = f2tf32(pa[i].w);
            *(uint4*)&As[r * 36 + c] = v;
        }
#pragma unroll
        for (int i = 0; i < 4; i++) {
            const int f = i * 256 + tid; const int r = f >> 5, c = (f & 31) << 2;
            uint4 v; v.x = f2tf32(pb[i].x); v.y = f2tf32(pb[i].y);
            v.z = f2tf32(pb[i].z); v.w = f2tf32(pb[i].w);
            *(uint4*)&Bs[r * 136 + c] = v;
        }
        __syncthreads();
    }
    compute_chunk<MT>(As, 36, Bs, acc, wm0, wn0, g, t4);
}

// A resident in smem (tf32, stride astr). B streamed from gmem.
template<int MT>
__device__ __forceinline__ void gemm_smemA(
    const uint32_t* __restrict__ Asrc, int astr, int K,
    const float* __restrict__ B, int ldb,
    uint32_t* Bs, float (&acc)[MT][4][4],
    int tid, int wm0, int wn0, int g, int t4)
{
    acc_zero<MT>(acc);
    float4 pb[4];
    const int nch = K >> 5;
    __syncthreads();
#pragma unroll
    for (int i = 0; i < 4; i++) {
        const int f = i * 256 + tid; const int r = f >> 5, c = (f & 31) << 2;
        pb[i] = *(const float4*)(B + (size_t)r * ldb + c);
    }
#pragma unroll
    for (int i = 0; i < 4; i++) {
        const int f = i * 256 + tid; const int r = f >> 5, c = (f & 31) << 2;
        uint4 v; v.x = f2tf32(pb[i].x); v.y = f2tf32(pb[i].y);
        v.z = f2tf32(pb[i].z); v.w = f2tf32(pb[i].w);
        *(uint4*)&Bs[r * 136 + c] = v;
    }
    __syncthreads();
    for (int ch = 1; ch < nch; ch++) {
        const int k0 = ch * 32;
#pragma unroll
        for (int i = 0; i < 4; i++) {
            const int f = i * 256 + tid; const int r = f >> 5, c = (f & 31) << 2;
            pb[i] = *(const float4*)(B + (size_t)(k0 + r) * ldb + c);
        }
        compute_chunk<MT>(Asrc + (ch - 1) * 32, astr, Bs, acc, wm0, wn0, g, t4);
        __syncthreads();
#pragma unroll
        for (int i = 0; i < 4; i++) {
            const int f = i * 256 + tid; const int r = f >> 5, c = (f & 31) << 2;
            uint4 v; v.x = f2tf32(pb[i].x); v.y = f2tf32(pb[i].y);
            v.z = f2tf32(pb[i].z); v.w = f2tf32(pb[i].w);
            *(uint4*)&Bs[r * 136 + c] = v;
        }
        __syncthreads();
    }
    compute_chunk<MT>(Asrc + (nch - 1) * 32, astr, Bs, acc, wm0, wn0, g, t4);
}

// ================= embed_gi: obs -> emb1 -> emb -> gi (M=64 tiles) =================
__global__ __launch_bounds__(256, 2) void embed_gi_fused(
    const float* __restrict__ obs,
    const float* __restrict__ e1w, const float* __restrict__ e1b,
    const float* __restrict__ e2w, const float* __restrict__ e2b,
    const float* __restrict__ Wi,  const float* __restrict__ bi,
    float* __restrict__ gi)
{
    extern __shared__ unsigned char smraw[];
    uint32_t* As = (uint32_t*)smraw;          // 64*36
    uint32_t* Bs = As + 64 * 36;              // 32*136
    uint32_t* s1 = Bs + 32 * 136;             // 64*132 (emb1 then emb, in place)

    const int tid = threadIdx.x;
    const int warp = tid >> 5, lane = tid & 31;
    const int g = lane >> 2, t4 = lane & 3;
    const int wm0 = (warp >> 2) * 32, wn0 = (warp & 3) * 32;
    const int br0 = blockIdx.x * 64;
    float acc[2][4][4];

    // emb1 = relu(obs @ e1w + b)
    gemm_gmemA<2>(obs + (size_t)br0 * 64, 64, 64, e1w, 128, As, Bs, acc, tid, wm0, wn0, g, t4);
    __syncthreads();
#pragma unroll
    for (int mt = 0; mt < 2; mt++)
#pragma unroll
        for (int nt = 0; nt < 4; nt++) {
            const int r0 = wm0 + mt * 16 + g, c0 = wn0 + nt * 8 + 2 * t4;
            const float b0 = e1b[c0], b1 = e1b[c0 + 1];
            s1[r0 * 132 + c0]           = f2tf32(fmaxf(acc[mt][nt][0] + b0, 0.f));
            s1[r0 * 132 + c0 + 1]       = f2tf32(fmaxf(acc[mt][nt][1] + b1, 0.f));
            s1[(r0 + 8) * 132 + c0]     = f2tf32(fmaxf(acc[mt][nt][2] + b0, 0.f));
            s1[(r0 + 8) * 132 + c0 + 1] = f2tf32(fmaxf(acc[mt][nt][3] + b1, 0.f));
        }

    // emb = relu(emb1 @ e2w + b), in place over s1
    gemm_smemA<2>(s1, 132, 128, e2w, 128, Bs, acc, tid, wm0, wn0, g, t4);
    __syncthreads();
#pragma unroll
    for (int mt = 0; mt < 2; mt++)
#pragma unroll
        for (int nt = 0; nt < 4; nt++) {
            const int r0 = wm0 + mt * 16 + g, c0 = wn0 + nt * 8 + 2 * t4;
            const float b0 = e2b[c0], b1 = e2b[c0 + 1];
            s1[r0 * 132 + c0]           = f2tf32(fmaxf(acc[mt][nt][0] + b0, 0.f));
            s1[r0 * 132 + c0 + 1]       = f2tf32(fmaxf(acc[mt][nt][1] + b1, 0.f));
            s1[(r0 + 8) * 132 + c0]     = f2tf32(fmaxf(acc[mt][nt][2] + b0, 0.f));
            s1[(r0 + 8) * 132 + c0 + 1] = f2tf32(fmaxf(acc[mt][nt][3] + b1, 0.f));
        }

    // gi = emb @ Wi + bi (3 n-passes)
    for (int p = 0; p < 3; p++) {
        gemm_smemA<2>(s1, 132, 128, Wi + p * 128, 384, Bs, acc, tid, wm0, wn0, g, t4);
#pragma unroll
        for (int mt = 0; mt < 2; mt++)
#pragma unroll
            for (int nt = 0; nt < 4; nt++) {
                const int r0 = wm0 + mt * 16 + g, c0 = wn0 + nt * 8 + 2 * t4;
                const int cg = p * 128 + c0;
                const float b0 = bi[cg], b1 = bi[cg + 1];
                float2 o0 = {acc[mt][nt][0] + b0, acc[mt][nt][1] + b1};
                float2 o1 = {acc[mt][nt][2] + b0, acc[mt][nt][3] + b1};
                *(float2*)(gi + (size_t)(br0 + r0) * 384 + cg) = o0;
                *(float2*)(gi + (size_t)(br0 + r0 + 8) * 384 + cg) = o1;
            }
    }
}

// ================= GRU (unchanged from R4) =================
__global__ __launch_bounds__(384, 1) void gru_kernel(
    const float* __restrict__ gi, const int* __restrict__ dones,
    const float* __restrict__ Wh, const float* __restrict__ bhn,
    const float* __restrict__ h0, float* __restrict__ e_out, float* __restrict__ h_out)
{
    __shared__ __align__(16) float hs[4 * 128];
    __shared__ float ghx[3 * 4 * 128];
    const int tid = threadIdx.x;
    const int col = tid & 127, gate = tid >> 7;
    const int rowbase = blockIdx.x * 4;

    ull w2[64];
#pragma unroll
    for (int j = 0; j < 64; j++) {
        const float wa = Wh[(size_t)(2 * j) * 384 + gate * 128 + col];
        const float wb = Wh[(size_t)(2 * j + 1) * 384 + gate * 128 + col];
        w2[j] = pack2(wa, wb);
    }
    for (int i = tid; i < 512; i += 384) {
        const int r = i >> 7, c = i & 127;
        const int d = dones[rowbase + r];
        hs[i] = d ? 0.f : h0[(size_t)(rowbase + r) * 128 + c];
    }
    const float bh = bhn[col];
    __syncthreads();

    const int r0 = gate;
    const bool has2 = (tid < 128);

    for (int t = 0; t < 128; t++) {
        const size_t gbase0 = ((size_t)(t * 512 + rowbase + r0)) * 384 + col;
        const float gr0 = gi[gbase0], gz0 = gi[gbase0 + 128], gn0 = gi[gbase0 + 256];
        const int dc0 = dones[t * 512 + rowbase + r0];
        const int dn0 = (t < 127) ? dones[(t + 1) * 512 + rowbase + r0] : 0;
        float gr1 = 0.f, gz1 = 0.f, gn1 = 0.f; int dc1 = 0, dn1 = 0;
        if (has2) {
            const size_t gbase1 = ((size_t)(t * 512 + rowbase + 3)) * 384 + col;
            gr1 = gi[gbase1]; gz1 = gi[gbase1 + 128]; gn1 = gi[gbase1 + 256];
            dc1 = dones[t * 512 + rowbase + 3];
            dn1 = (t < 127) ? dones[(t + 1) * 512 + rowbase + 3] : 0;
        }

        ull acc0 = 0ull, acc1 = 0ull, acc2 = 0ull, acc3 = 0ull;
        const double2* hp = (const double2*)hs;
#pragma unroll
        for (int jj = 0; jj < 32; jj++) {
            const ull wA = w2[2 * jj], wB = w2[2 * jj + 1];
            const double2 h0v = hp[jj];
            const double2 h1v = hp[32 + jj];
            const double2 h2v = hp[64 + jj];
            const double2 h3v = hp[96 + jj];
            acc0 = fma2(wA, __double_as_longlong(h0v.x), acc0);
            acc1 = fma2(wA, __double_as_longlong(h1v.x), acc1);
            acc2 = fma2(wA, __double_as_longlong(h2v.x), acc2);
            acc3 = fma2(wA, __double_as_longlong(h3v.x), acc3);
            acc0 = fma2(wB, __double_as_longlong(h0v.y), acc0);
            acc1 = fma2(wB, __double_as_longlong(h1v.y), acc1);
            acc2 = fma2(wB, __double_as_longlong(h2v.y), acc2);
            acc3 = fma2(wB, __double_as_longlong(h3v.y), acc3);
        }
        {
            float a, b;
            unpack2(acc0, a, b); ghx[(gate * 4 + 0) * 128 + col] = a + b;
            unpack2(acc1, a, b); ghx[(gate * 4 + 1) * 128 + col] = a + b;
            unpack2(acc2, a, b); ghx[(gate * 4 + 2) * 128 + col] = a + b;
            unpack2(acc3, a, b); ghx[(gate * 4 + 3) * 128 + col] = a + b;
        }
        __syncthreads();

        {
            const float ar = ghx[(0 * 4 + r0) * 128 + col];
            const float az = ghx[(1 * 4 + r0) * 128 + col];
            const float an = ghx[(2 * 4 + r0) * 128 + col];
            const float hold = hs[r0 * 128 + col];
            const float r = 1.f / (1.f + expf(-(gr0 + ar)));
            const float z = 1.f / (1.f + expf(-(gz0 + az)));
            const float n = tanhf(gn0 + r * (an + bh));
            const float hnew = (1.f - z) * n + z * hold;
            e_out[((size_t)(t * 512 + rowbase + r0)) * 128 + col] = dc0 ? 0.f : hnew;
            hs[r0 * 128 + col] = dn0 ? 0.f : hnew;
        }
        if (has2) {
            const float ar = ghx[(0 * 4 + 3) * 128 + col];
            const float az = ghx[(1 * 4 + 3) * 128 + col];
            const float an = ghx[(2 * 4 + 3) * 128 + col];
            const float hold = hs[3 * 128 + col];
            const float r = 1.f / (1.f + expf(-(gr1 + ar)));
            const float z = 1.f / (1.f + expf(-(gz1 + az)));
            const float n = tanhf(gn1 + r * (an + bh));
            const float hnew = (1.f - z) * n + z * hold;
            e_out[((size_t)(t * 512 + rowbase + 3)) * 128 + col] = dc1 ? 0.f : hnew;
            hs[3 * 128 + col] = dn1 ? 0.f : hnew;
        }
        __syncthreads();
    }
    for (int i = tid; i < 512; i += 384) {
        const int r = i >> 7, c = i & 127;
        h_out[(size_t)(rowbase + r) * 128 + c] = hs[i];
    }
}

// ================= megakernel: 2x(couple+delta) + value per 64-row block ======
__global__ __launch_bounds__(256, 2) void post_gru_mega(
    float* __restrict__ e, const int* __restrict__ dones,
    const float* __restrict__ chw, const float* __restrict__ chb,
    const float* __restrict__ cow, const float* __restrict__ cob,
    const float* __restrict__ uhw, const float* __restrict__ uhb,
    const float* __restrict__ uow, const float* __restrict__ uob,
    const float* __restrict__ v1w, const float* __restrict__ v1b,
    const float* __restrict__ v2w, const float* __restrict__ v2b,
    const float* __restrict__ vow, const float* __restrict__ vob,
    float* __restrict__ values)
{
    extern __shared__ unsigned char smraw[];
    uint32_t* As   = (uint32_t*)smraw;         // 64*36   = 2304
    uint32_t* Bs   = As + 64 * 36;             // 32*136  = 4352
    uint32_t* U    = Bs + 32 * 136;            // 16896 (union: sai+saj | cat | d1s | v1s)
    float* sC      = (float*)(U + 16896);      // 512
    float* salive  = sC + 512;                 // 64
    float* scb     = salive + 64;              // 128
    float* sw      = scb + 128;                // 128
    float* sred    = sw + 128;                 // 256
    float* sai     = (float*)U;                // 64*132
    float* saj     = sai + 64 * 132;           // 64*132

    const int tid = threadIdx.x;
    const int warp = tid >> 5, lane = tid & 31;
    const int g = lane >> 2, t4 = lane & 3;
    const int wm0 = (warp >> 2) * 32, wn0 = (warp & 3) * 32;
    const int br0 = blockIdx.x * 64;
    float acc[2][4][4];

    if (tid < 128) { scb[tid] = chb[tid]; sw[tid] = cow[tid]; }
    if (tid < 64) salive[tid] = (dones[br0 + tid] == 0) ? 1.f : 0.f;
    const float cob0 = __ldg(cob);

    for (int it = 0; it < 2; it++) {
        // --- ai/aj GEMMs (fp32 results into sai/saj) ---
        for (int p = 0; p < 2; p++) {
            gemm_gmemA<2>(e + (size_t)br0 * 128, 128, 128, chw + p * 128 * 128, 128,
                          As, Bs, acc, tid, wm0, wn0, g, t4);
            float* dst = p ? saj : sai;
            __syncthreads();
#pragma unroll
            for (int mt = 0; mt < 2; mt++)
#pragma unroll
                for (int nt = 0; nt < 4; nt++) {
                    const int r0 = wm0 + mt * 16 + g, c0 = wn0 + nt * 8 + 2 * t4;
                    dst[r0 * 132 + c0]           = acc[mt][nt][0];
                    dst[r0 * 132 + c0 + 1]       = acc[mt][nt][1];
                    dst[(r0 + 8) * 132 + c0]     = acc[mt][nt][2];
                    dst[(r0 + 8) * 132 + c0 + 1] = acc[mt][nt][3];
                }
        }
        __syncthreads();

        // --- pairwise: 8 groups x 64 pairs; warp = group, thread -> (i, j-pair) ---
        {
            const int grp = tid >> 5, s = tid & 31;
            const int i = s >> 2, jh = s & 3;
            float a2[2] = {0.f, 0.f};
#pragma unroll 8
            for (int h = 0; h < 128; h += 4) {
                const float4 av = *(const float4*)&sai[(grp * 8 + i) * 132 + h];
                const float4 cb = *(const float4*)&scb[h];
                const float4 wv = *(const float4*)&sw[h];
#pragma unroll
                for (int jj = 0; jj < 2; jj++) {
                    const int j = jh * 2 + jj;
                    const float4 bv = *(const float4*)&saj[(grp * 8 + j) * 132 + h];
                    a2[jj] = fmaf(fmaxf(av.x + bv.x + cb.x, 0.f), wv.x, a2[jj]);
                    a2[jj] = fmaf(fmaxf(av.y + bv.y + cb.y, 0.f), wv.y, a2[jj]);
                    a2[jj] = fmaf(fmaxf(av.z + bv.z + cb.z, 0.f), wv.z, a2[jj]);
                    a2[jj] = fmaf(fmaxf(av.w + bv.w + cb.w, 0.f), wv.w, a2[jj]);
                }
            }
#pragma unroll
            for (int jj = 0; jj < 2; jj++) {
                const int j = jh * 2 + jj;
                float c = 1.f / (1.f + expf(-(a2[jj] + cob0)));
                c *= salive[grp * 8 + j];
                if (i == j) c = 0.f;
                sC[grp * 64 + i * 8 + j] = c;
            }
        }
        __syncthreads();

        // --- context: write cat (tf32, stride 260) over sai/saj region ---
        {
            const int colt = tid & 127, gh = tid >> 7;
#pragma unroll
            for (int gg = 0; gg < 4; gg++) {
                const int grp = gh * 4 + gg;
                const int rbase = br0 + grp * 8;
                float ev[8];
#pragma unroll
                for (int j = 0; j < 8; j++) ev[j] = e[(size_t)(rbase + j) * 128 + colt];
#pragma unroll
                for (int i = 0; i < 8; i++) {
                    float ctx = 0.f;
#pragma unroll
                    for (int j = 0; j < 8; j++)
                        ctx = fmaf(sC[grp * 64 + i * 8 + j], ev[j], ctx);
                    U[(grp * 8 + i) * 260 + colt]       = f2tf32(ev[i]);
                    U[(grp * 8 + i) * 260 + 128 + colt] = f2tf32(ctx);
                }
            }
        }
        __syncthreads();

        // --- d1 = relu(cat @ Uh + b): cat in U (K=256), result tf32 over U (132) ---
        gemm_smemA<2>(U, 260, 256, uhw, 128, Bs, acc, tid, wm0, wn0, g, t4);
        __syncthreads();
#pragma unroll
        for (int mt = 0; mt < 2; mt++)
#pragma unroll
            for (int nt = 0; nt < 4; nt++) {
                const int r0 = wm0 + mt * 16 + g, c0 = wn0 + nt * 8 + 2 * t4;
                const float b0 = uhb[c0], b1 = uhb[c0 + 1];
                U[r0 * 132 + c0]           = f2tf32(fmaxf(acc[mt][nt][0] + b0, 0.f));
                U[r0 * 132 + c0 + 1]       = f2tf32(fmaxf(acc[mt][nt][1] + b1, 0.f));
                U[(r0 + 8) * 132 + c0]     = f2tf32(fmaxf(acc[mt][nt][2] + b0, 0.f));
                U[(r0 + 8) * 132 + c0 + 1] = f2tf32(fmaxf(acc[mt][nt][3] + b1, 0.f));
            }

        // --- e = (e + relu(d1 @ Uo + b)) * alive ---
        gemm_smemA<2>(U, 132, 128, uow, 128, Bs, acc, tid, wm0, wn0, g, t4);
#pragma unroll
        for (int mt = 0; mt < 2; mt++) {
            const int r0 = wm0 + mt * 16 + g;
            const float al0 = salive[r0];
            const float al1 = salive[r0 + 8];
#pragma unroll
            for (int nt = 0; nt < 4; nt++) {
                const int c0 = wn0 + nt * 8 + 2 * t4;
                const float b0 = uob[c0], b1 = uob[c0 + 1];
                float* p0 = e + (size_t)(br0 + r0) * 128 + c0;
                float* p1 = e + (size_t)(br0 + r0 + 8) * 128 + c0;
                const float2 e0 = *(const float2*)p0;
                const float2 e1 = *(const float2*)p1;
                float2 o0, o1;
                o0.x = (e0.x + fmaxf(acc[mt][nt][0] + b0, 0.f)) * al0;
                o0.y = (e0.y + fmaxf(acc[mt][nt][1] + b1, 0.f)) * al0;
                o1.x = (e1.x + fmaxf(acc[mt][nt][2] + b0, 0.f)) * al1;
                o1.y = (e1.y + fmaxf(acc[mt][nt][3] + b1, 0.f)) * al1;
                *(float2*)p0 = o0;
                *(float2*)p1 = o1;
            }
        }
        __syncthreads();   // e writes visible to whole block before next iter reads
    }

    // --- value head: v1 = relu(e @ W1 + b) into U (stride 260) ---
    for (int p = 0; p < 2; p++) {
        gemm_gmemA<2>(e + (size_t)br0 * 128, 128, 128, v1w + p * 128, 256,
                      As, Bs, acc, tid, wm0, wn0, g, t4);
        __syncthreads();
#pragma unroll
        for (int mt = 0; mt < 2; mt++)
#pragma unroll
            for (int nt = 0; nt < 4; nt++) {
                const int r0 = wm0 + mt * 16 + g, c0 = wn0 + nt * 8 + 2 * t4;
                const int cg = p * 128 + c0;
                const float b0 = v1b[cg], b1 = v1b[cg + 1];
                U[r0 * 260 + cg]           = f2tf32(fmaxf(acc[mt][nt][0] + b0, 0.f));
                U[r0 * 260 + cg + 1]       = f2tf32(fmaxf(acc[mt][nt][1] + b1, 0.f));
                U[(r0 + 8) * 260 + cg]     = f2tf32(fmaxf(acc[mt][nt][2] + b0, 0.f));
                U[(r0 + 8) * 260 + cg + 1] = f2tf32(fmaxf(acc[mt][nt][3] + b1, 0.f));
            }
    }

    // --- v2 = relu(v1 @ W2 + b), folded into vow reduction ---
    float part[2][2];
    part[0][0] = part[0][1] = part[1][0] = part[1][1] = 0.f;
    for (int p = 0; p < 2; p++) {
        gemm_smemA<2>(U, 260, 256, v2w + p * 128, 256, Bs, acc, tid, wm0, wn0, g, t4);
#pragma unroll
        for (int mt = 0; mt < 2; mt++)
#pragma unroll
            for (int nt = 0; nt < 4; nt++) {
                const int c0 = wn0 + nt * 8 + 2 * t4;
                const int cg = p * 128 + c0;
                const float b0 = v2b[cg], b1 = v2b[cg + 1];
                const float w0 = vow[cg], w1 = vow[cg + 1];
                part[mt][0] = fmaf(fmaxf(acc[mt][nt][0] + b0, 0.f), w0, part[mt][0]);
                part[mt][0] = fmaf(fmaxf(acc[mt][nt][1] + b1, 0.f), w1, part[mt][0]);
                part[mt][1] = fmaf(fmaxf(acc[mt][nt][2] + b0, 0.f), w0, part[mt][1]);
                part[mt][1] = fmaf(fmaxf(acc[mt][nt][3] + b1, 0.f), w1, part[mt][1]);
            }
    }
#pragma unroll
    for (int mt = 0; mt < 2; mt++)
#pragma unroll
        for (int h = 0; h < 2; h++) {
            part[mt][h] += __shfl_xor_sync(0xffffffffu, part[mt][h], 1);
            part[mt][h] += __shfl_xor_sync(0xffffffffu, part[mt][h], 2);
        }
    __syncthreads();
    if (t4 == 0) {
        const int wn = warp & 3;
#pragma unroll
        for (int mt = 0; mt < 2; mt++)
#pragma unroll
            for (int h = 0; h < 2; h++)
                sred[wn * 64 + wm0 + mt * 16 + g + h * 8] = part[mt][h];
    }
    __syncthreads();
    if (tid < 64) {
        values[br0 + tid] = sred[tid] + sred[64 + tid] + sred[128 + tid]
                          + sred[192 + tid] + __ldg(vob);
    }
}

// ================= launch =================
extern "C" void kernel_launch(void* const* d_in, const int* in_sizes, int n_in,
                              void* d_out, int out_size)
{
    const float* hidden = (const float*)d_in[0];
    const float* obs    = (const float*)d_in[1];
    const int*   dones  = (const int*)d_in[2];
    const float* e1w = (const float*)d_in[3];
    const float* e1b = (const float*)d_in[4];
    const float* e2w = (const float*)d_in[5];
    const float* e2b = (const float*)d_in[6];
    const float* Wi  = (const float*)d_in[7];
    const float* bi  = (const float*)d_in[8];
    const float* Wh  = (const float*)d_in[9];
    const float* bhn = (const float*)d_in[10];
    const float* chw = (const float*)d_in[11];
    const float* chb = (const float*)d_in[12];
    const float* cow = (const float*)d_in[13];
    const float* cob = (const float*)d_in[14];
    const float* uhw = (const float*)d_in[15];
    const float* uhb = (const float*)d_in[16];
    const float* uow = (const float*)d_in[17];
    const float* uob = (const float*)d_in[18];
    const float* v1w = (const float*)d_in[19];
    const float* v1b = (const float*)d_in[20];
    const float* v2w = (const float*)d_in[21];
    const float* v2b = (const float*)d_in[22];
    const float* vow = (const float*)d_in[23];
    const float* vob = (const float*)d_in[24];
    float* out = (float*)d_out;

    float *gi, *e;
    cudaGetSymbolAddress((void**)&gi, g_gi);
    cudaGetSymbolAddress((void**)&e,  g_e);

    const int smE = (64 * 36 + 32 * 136 + 64 * 132) * 4;
    const int smM = (64 * 36 + 32 * 136 + 16896 + 512 + 64 + 128 + 128 + 256) * 4;
    cudaFuncSetAttribute(embed_gi_fused, cudaFuncAttributeMaxDynamicSharedMemorySize, smE);
    cudaFuncSetAttribute(post_gru_mega,  cudaFuncAttributeMaxDynamicSharedMemorySize, smM);

    embed_gi_fused<<<1024, 256, smE>>>(obs, e1w, e1b, e2w, e2b, Wi, bi, gi);
    gru_kernel<<<128, 384>>>(gi, dones, Wh, bhn, hidden, e, out);
    post_gru_mega<<<1024, 256, smM>>>(e, dones, chw, chb, cow, cob,
                                      uhw, uhb, uow, uob,
                                      v1w, v1b, v2w, v2b, vow, vob, out + 65536);
}

// round 9
// speedup vs baseline: 1.4564x; 1.4564x over previous
#include <cuda_runtime.h>
#include <cstdint>
#include <cstddef>

// CriticRNN: T=128, NE=64, NA=8, OBS=64, D=128, CH=128, VH=256, ITERS=2, B=512
// Round 7: MT=4 (128-row) tiles restored + full post-GRU fusion + ping-pong
// staging (1 barrier per k-chunk). 3 launches: embed_gi -> gru -> mega.

#define TBROWS 65536
typedef unsigned long long ull;

__device__ float g_gi[(size_t)TBROWS * 384];
__device__ float g_e [(size_t)TBROWS * 128];

__device__ __forceinline__ uint32_t f2tf32(float x) {
    uint32_t u; asm("cvt.rna.tf32.f32 %0, %1;" : "=r"(u) : "f"(x)); return u;
}
__device__ __forceinline__ ull pack2(float lo, float hi) {
    ull r; asm("mov.b64 %0, {%1, %2};" : "=l"(r) : "f"(lo), "f"(hi)); return r;
}
__device__ __forceinline__ void unpack2(ull v, float& a, float& b) {
    asm("mov.b64 {%0, %1}, %2;" : "=f"(a), "=f"(b) : "l"(v));
}
__device__ __forceinline__ ull fma2(ull a, ull b, ull c) {
    ull d; asm("fma.rn.f32x2 %0, %1, %2, %3;" : "=l"(d) : "l"(a), "l"(b), "l"(c));
    return d;
}
__device__ __forceinline__ void mma8(float c[4],
    uint32_t a0, uint32_t a1, uint32_t a2, uint32_t a3, uint32_t b0, uint32_t b1)
{
    asm volatile(
        "mma.sync.aligned.m16n8k8.row.col.f32.tf32.tf32.f32 "
        "{%0,%1,%2,%3},{%4,%5,%6,%7},{%8,%9},{%0,%1,%2,%3};"
        : "+f"(c[0]), "+f"(c[1]), "+f"(c[2]), "+f"(c[3])
        : "r"(a0), "r"(a1), "r"(a2), "r"(a3), "r"(b0), "r"(b1));
}

// ===== GEMM blocks: tile 128x128, 8 warps (2m x 4n), warp 64x32, k-chunk 32 =====

__device__ __forceinline__ void acc_zero(float (&acc)[4][4][4]) {
#pragma unroll
    for (int mt = 0; mt < 4; mt++)
#pragma unroll
        for (int nt = 0; nt < 4; nt++)
#pragma unroll
            for (int q = 0; q < 4; q++) acc[mt][nt][q] = 0.f;
}

__device__ __forceinline__ void compute_chunk(
    const uint32_t* __restrict__ asrc, int astr, const uint32_t* __restrict__ Bs,
    float (&acc)[4][4][4], int wm0, int wn0, int g, int t4)
{
#pragma unroll
    for (int ks = 0; ks < 4; ks++) {
        const int kc = ks * 8 + t4;
        uint32_t af[4][4], bf[4][2];
#pragma unroll
        for (int mt = 0; mt < 4; mt++) {
            const int r = wm0 + mt * 16 + g;
            af[mt][0] = asrc[r * astr + kc];
            af[mt][1] = asrc[(r + 8) * astr + kc];
            af[mt][2] = asrc[r * astr + kc + 4];
            af[mt][3] = asrc[(r + 8) * astr + kc + 4];
        }
#pragma unroll
        for (int nt = 0; nt < 4; nt++) {
            const int c = wn0 + nt * 8 + g;
            bf[nt][0] = Bs[kc * 136 + c];
            bf[nt][1] = Bs[(kc + 4) * 136 + c];
        }
#pragma unroll
        for (int mt = 0; mt < 4; mt++)
#pragma unroll
            for (int nt = 0; nt < 4; nt++)
                mma8(acc[mt][nt], af[mt][0], af[mt][1], af[mt][2], af[mt][3],
                     bf[nt][0], bf[nt][1]);
    }
}

#define LDGA(k0)                                                               \
    _Pragma("unroll")                                                          \
    for (int i = 0; i < 4; i++) {                                              \
        const int f = i * 256 + tid; const int r = f >> 3, c = (f & 7) << 2;   \
        pa[i] = *(const float4*)(A + (size_t)r * lda + (k0) + c);              \
    }
#define LDGB(k0)                                                               \
    _Pragma("unroll")                                                          \
    for (int i = 0; i < 4; i++) {                                              \
        const int f = i * 256 + tid; const int r = f >> 5, c = (f & 31) << 2;  \
        pb[i] = *(const float4*)(B + (size_t)((k0) + r) * ldb + c);            \
    }
#define STSA(dst)                                                              \
    _Pragma("unroll")                                                          \
    for (int i = 0; i < 4; i++) {                                              \
        const int f = i * 256 + tid; const int r = f >> 3, c = (f & 7) << 2;   \
        uint4 v; v.x = f2tf32(pa[i].x); v.y = f2tf32(pa[i].y);                 \
        v.z = f2tf32(pa[i].z); v.w = f2tf32(pa[i].w);                          \
        *(uint4*)&(dst)[r * 36 + c] = v;                                       \
    }
#define STSB(dst)                                                              \
    _Pragma("unroll")                                                          \
    for (int i = 0; i < 4; i++) {                                              \
        const int f = i * 256 + tid; const int r = f >> 5, c = (f & 31) << 2;  \
        uint4 v; v.x = f2tf32(pb[i].x); v.y = f2tf32(pb[i].y);                 \
        v.z = f2tf32(pb[i].z); v.w = f2tf32(pb[i].w);                          \
        *(uint4*)&(dst)[r * 136 + c] = v;                                      \
    }

// A streamed from gmem; ping-pong As/Bs; one barrier per chunk.
__device__ __forceinline__ void gemm_gmemA(
    const float* __restrict__ A, int lda, int K,
    const float* __restrict__ B, int ldb,
    uint32_t* As0, uint32_t* As1, uint32_t* Bs0, uint32_t* Bs1,
    float (&acc)[4][4][4], int tid, int wm0, int wn0, int g, int t4)
{
    acc_zero(acc);
    float4 pa[4], pb[4];
    const int nch = K >> 5;
    uint32_t *Ac = As0, *An = As1, *Bc = Bs0, *Bn = Bs1;
    __syncthreads();                 // staging safe from previous pass readers
    LDGA(0) LDGB(0)
    STSA(Ac) STSB(Bc)
    __syncthreads();
    for (int ch = 1; ch < nch; ch++) {
        LDGA(ch * 32) LDGB(ch * 32)
        compute_chunk(Ac, 36, Bc, acc, wm0, wn0, g, t4);
        STSA(An) STSB(Bn)
        __syncthreads();
        uint32_t* t;
        t = Ac; Ac = An; An = t;
        t = Bc; Bc = Bn; Bn = t;
    }
    compute_chunk(Ac, 36, Bc, acc, wm0, wn0, g, t4);
}

// A resident in smem (tf32, stride astr); B streamed, Bs ping-pong.
__device__ __forceinline__ void gemm_smemA(
    const uint32_t* __restrict__ Asrc, int astr, int K,
    const float* __restrict__ B, int ldb,
    uint32_t* Bs0, uint32_t* Bs1,
    float (&acc)[4][4][4], int tid, int wm0, int wn0, int g, int t4)
{
    acc_zero(acc);
    float4 pb[4];
    const int nch = K >> 5;
    uint32_t *Bc = Bs0, *Bn = Bs1;
    __syncthreads();
    LDGB(0)
    STSB(Bc)
    __syncthreads();
    for (int ch = 1; ch < nch; ch++) {
        LDGB(ch * 32)
        compute_chunk(Asrc + (ch - 1) * 32, astr, Bc, acc, wm0, wn0, g, t4);
        STSB(Bn)
        __syncthreads();
        uint32_t* t = Bc; Bc = Bn; Bn = t;
    }
    compute_chunk(Asrc + (nch - 1) * 32, astr, Bc, acc, wm0, wn0, g, t4);
}

// ================= embed_gi: obs -> emb1 -> emb -> gi =================
__global__ __launch_bounds__(256) void embed_gi_fused(
    const float* __restrict__ obs,
    const float* __restrict__ e1w, const float* __restrict__ e1b,
    const float* __restrict__ e2w, const float* __restrict__ e2b,
    const float* __restrict__ Wi,  const float* __restrict__ bi,
    float* __restrict__ gi)
{
    extern __shared__ unsigned char smraw[];
    uint32_t* As0 = (uint32_t*)smraw;       // 128*36
    uint32_t* As1 = As0 + 128 * 36;
    uint32_t* Bs0 = As1 + 128 * 36;         // 32*136
    uint32_t* Bs1 = Bs0 + 32 * 136;
    uint32_t* s1  = Bs1 + 32 * 136;         // 128*132 (emb1 then emb in place)

    const int tid = threadIdx.x;
    const int warp = tid >> 5, lane = tid & 31;
    const int g = lane >> 2, t4 = lane & 3;
    const int wm0 = (warp >> 2) * 64, wn0 = (warp & 3) * 32;
    const int br0 = blockIdx.x * 128;
    float acc[4][4][4];

    // emb1 = relu(obs @ e1w + b)
    gemm_gmemA(obs + (size_t)br0 * 64, 64, 64, e1w, 128,
               As0, As1, Bs0, Bs1, acc, tid, wm0, wn0, g, t4);
    __syncthreads();
#pragma unroll
    for (int mt = 0; mt < 4; mt++)
#pragma unroll
        for (int nt = 0; nt < 4; nt++) {
            const int r0 = wm0 + mt * 16 + g, c0 = wn0 + nt * 8 + 2 * t4;
            const float b0 = e1b[c0], b1 = e1b[c0 + 1];
            s1[r0 * 132 + c0]           = f2tf32(fmaxf(acc[mt][nt][0] + b0, 0.f));
            s1[r0 * 132 + c0 + 1]       = f2tf32(fmaxf(acc[mt][nt][1] + b1, 0.f));
            s1[(r0 + 8) * 132 + c0]     = f2tf32(fmaxf(acc[mt][nt][2] + b0, 0.f));
            s1[(r0 + 8) * 132 + c0 + 1] = f2tf32(fmaxf(acc[mt][nt][3] + b1, 0.f));
        }

    // emb = relu(emb1 @ e2w + b), in place over s1
    gemm_smemA(s1, 132, 128, e2w, 128, Bs0, Bs1, acc, tid, wm0, wn0, g, t4);
    __syncthreads();   // all reads of s1 done before overwrite
#pragma unroll
    for (int mt = 0; mt < 4; mt++)
#pragma unroll
        for (int nt = 0; nt < 4; nt++) {
            const int r0 = wm0 + mt * 16 + g, c0 = wn0 + nt * 8 + 2 * t4;
            const float b0 = e2b[c0], b1 = e2b[c0 + 1];
            s1[r0 * 132 + c0]           = f2tf32(fmaxf(acc[mt][nt][0] + b0, 0.f));
            s1[r0 * 132 + c0 + 1]       = f2tf32(fmaxf(acc[mt][nt][1] + b1, 0.f));
            s1[(r0 + 8) * 132 + c0]     = f2tf32(fmaxf(acc[mt][nt][2] + b0, 0.f));
            s1[(r0 + 8) * 132 + c0 + 1] = f2tf32(fmaxf(acc[mt][nt][3] + b1, 0.f));
        }

    // gi = emb @ Wi + bi (3 n-passes)
    for (int p = 0; p < 3; p++) {
        gemm_smemA(s1, 132, 128, Wi + p * 128, 384, Bs0, Bs1, acc, tid, wm0, wn0, g, t4);
#pragma unroll
        for (int mt = 0; mt < 4; mt++)
#pragma unroll
            for (int nt = 0; nt < 4; nt++) {
                const int r0 = wm0 + mt * 16 + g, c0 = wn0 + nt * 8 + 2 * t4;
                const int cg = p * 128 + c0;
                const float b0 = bi[cg], b1 = bi[cg + 1];
                float2 o0 = {acc[mt][nt][0] + b0, acc[mt][nt][1] + b1};
                float2 o1 = {acc[mt][nt][2] + b0, acc[mt][nt][3] + b1};
                *(float2*)(gi + (size_t)(br0 + r0) * 384 + cg) = o0;
                *(float2*)(gi + (size_t)(br0 + r0 + 8) * 384 + cg) = o1;
            }
    }
}

// ================= GRU (unchanged) =================
__global__ __launch_bounds__(384, 1) void gru_kernel(
    const float* __restrict__ gi, const int* __restrict__ dones,
    const float* __restrict__ Wh, const float* __restrict__ bhn,
    const float* __restrict__ h0, float* __restrict__ e_out, float* __restrict__ h_out)
{
    __shared__ __align__(16) float hs[4 * 128];
    __shared__ float ghx[3 * 4 * 128];
    const int tid = threadIdx.x;
    const int col = tid & 127, gate = tid >> 7;
    const int rowbase = blockIdx.x * 4;

    ull w2[64];
#pragma unroll
    for (int j = 0; j < 64; j++) {
        const float wa = Wh[(size_t)(2 * j) * 384 + gate * 128 + col];
        const float wb = Wh[(size_t)(2 * j + 1) * 384 + gate * 128 + col];
        w2[j] = pack2(wa, wb);
    }
    for (int i = tid; i < 512; i += 384) {
        const int r = i >> 7, c = i & 127;
        const int d = dones[rowbase + r];
        hs[i] = d ? 0.f : h0[(size_t)(rowbase + r) * 128 + c];
    }
    const float bh = bhn[col];
    __syncthreads();

    const int r0 = gate;
    const bool has2 = (tid < 128);

    for (int t = 0; t < 128; t++) {
        const size_t gbase0 = ((size_t)(t * 512 + rowbase + r0)) * 384 + col;
        const float gr0 = gi[gbase0], gz0 = gi[gbase0 + 128], gn0 = gi[gbase0 + 256];
        const int dc0 = dones[t * 512 + rowbase + r0];
        const int dn0 = (t < 127) ? dones[(t + 1) * 512 + rowbase + r0] : 0;
        float gr1 = 0.f, gz1 = 0.f, gn1 = 0.f; int dc1 = 0, dn1 = 0;
        if (has2) {
            const size_t gbase1 = ((size_t)(t * 512 + rowbase + 3)) * 384 + col;
            gr1 = gi[gbase1]; gz1 = gi[gbase1 + 128]; gn1 = gi[gbase1 + 256];
            dc1 = dones[t * 512 + rowbase + 3];
            dn1 = (t < 127) ? dones[(t + 1) * 512 + rowbase + 3] : 0;
        }

        ull acc0 = 0ull, acc1 = 0ull, acc2 = 0ull, acc3 = 0ull;
        const double2* hp = (const double2*)hs;
#pragma unroll
        for (int jj = 0; jj < 32; jj++) {
            const ull wA = w2[2 * jj], wB = w2[2 * jj + 1];
            const double2 h0v = hp[jj];
            const double2 h1v = hp[32 + jj];
            const double2 h2v = hp[64 + jj];
            const double2 h3v = hp[96 + jj];
            acc0 = fma2(wA, __double_as_longlong(h0v.x), acc0);
            acc1 = fma2(wA, __double_as_longlong(h1v.x), acc1);
            acc2 = fma2(wA, __double_as_longlong(h2v.x), acc2);
            acc3 = fma2(wA, __double_as_longlong(h3v.x), acc3);
            acc0 = fma2(wB, __double_as_longlong(h0v.y), acc0);
            acc1 = fma2(wB, __double_as_longlong(h1v.y), acc1);
            acc2 = fma2(wB, __double_as_longlong(h2v.y), acc2);
            acc3 = fma2(wB, __double_as_longlong(h3v.y), acc3);
        }
        {
            float a, b;
            unpack2(acc0, a, b); ghx[(gate * 4 + 0) * 128 + col] = a + b;
            unpack2(acc1, a, b); ghx[(gate * 4 + 1) * 128 + col] = a + b;
            unpack2(acc2, a, b); ghx[(gate * 4 + 2) * 128 + col] = a + b;
            unpack2(acc3, a, b); ghx[(gate * 4 + 3) * 128 + col] = a + b;
        }
        __syncthreads();

        {
            const float ar = ghx[(0 * 4 + r0) * 128 + col];
            const float az = ghx[(1 * 4 + r0) * 128 + col];
            const float an = ghx[(2 * 4 + r0) * 128 + col];
            const float hold = hs[r0 * 128 + col];
            const float r = 1.f / (1.f + expf(-(gr0 + ar)));
            const float z = 1.f / (1.f + expf(-(gz0 + az)));
            const float n = tanhf(gn0 + r * (an + bh));
            const float hnew = (1.f - z) * n + z * hold;
            e_out[((size_t)(t * 512 + rowbase + r0)) * 128 + col] = dc0 ? 0.f : hnew;
            hs[r0 * 128 + col] = dn0 ? 0.f : hnew;
        }
        if (has2) {
            const float ar = ghx[(0 * 4 + 3) * 128 + col];
            const float az = ghx[(1 * 4 + 3) * 128 + col];
            const float an = ghx[(2 * 4 + 3) * 128 + col];
            const float hold = hs[3 * 128 + col];
            const float r = 1.f / (1.f + expf(-(gr1 + ar)));
            const float z = 1.f / (1.f + expf(-(gz1 + az)));
            const float n = tanhf(gn1 + r * (an + bh));
            const float hnew = (1.f - z) * n + z * hold;
            e_out[((size_t)(t * 512 + rowbase + 3)) * 128 + col] = dc1 ? 0.f : hnew;
            hs[3 * 128 + col] = dn1 ? 0.f : hnew;
        }
        __syncthreads();
    }
    for (int i = tid; i < 512; i += 384) {
        const int r = i >> 7, c = i & 127;
        h_out[(size_t)(rowbase + r) * 128 + c] = hs[i];
    }
}

// ============ mega: 2x(couple+delta) + value head per 128-row block ============
__global__ __launch_bounds__(256) void post_gru_mega(
    float* __restrict__ e, const int* __restrict__ dones,
    const float* __restrict__ chw, const float* __restrict__ chb,
    const float* __restrict__ cow, const float* __restrict__ cob,
    const float* __restrict__ uhw, const float* __restrict__ uhb,
    const float* __restrict__ uow, const float* __restrict__ uob,
    const float* __restrict__ v1w, const float* __restrict__ v1b,
    const float* __restrict__ v2w, const float* __restrict__ v2b,
    const float* __restrict__ vow, const float* __restrict__ vob,
    float* __restrict__ values)
{
    extern __shared__ unsigned char smraw[];
    uint32_t* As0 = (uint32_t*)smraw;            // 128*36
    uint32_t* As1 = As0 + 128 * 36;
    uint32_t* Bs0 = As1 + 128 * 36;              // 32*136
    uint32_t* Bs1 = Bs0 + 32 * 136;
    uint32_t* U   = Bs1 + 32 * 136;              // 128*264 union (sai+saj | cat | d1 | v1)
    float* sC     = (float*)(U + 128 * 264);     // 1024
    float* salive = sC + 1024;                   // 128
    float* scb    = salive + 128;                // 128
    float* sw     = scb + 128;                   // 128
    float* sred   = sw + 128;                    // 512
    float* sai    = (float*)U;                   // 128*132
    float* saj    = sai + 128 * 132;             // 128*132

    const int tid = threadIdx.x;
    const int warp = tid >> 5, lane = tid & 31;
    const int g = lane >> 2, t4 = lane & 3;
    const int wm0 = (warp >> 2) * 64, wn0 = (warp & 3) * 32;
    const int br0 = blockIdx.x * 128;
    float acc[4][4][4];

    if (tid < 128) {
        scb[tid] = chb[tid];
        sw[tid]  = cow[tid];
        salive[tid] = (dones[br0 + tid] == 0) ? 1.f : 0.f;
    }
    const float cob0 = __ldg(cob);

    for (int it = 0; it < 2; it++) {
        // ai/aj GEMMs -> sai/saj (fp32)
        for (int p = 0; p < 2; p++) {
            gemm_gmemA(e + (size_t)br0 * 128, 128, 128, chw + p * 128 * 128, 128,
                       As0, As1, Bs0, Bs1, acc, tid, wm0, wn0, g, t4);
            float* dst = p ? saj : sai;
#pragma unroll
            for (int mt = 0; mt < 4; mt++)
#pragma unroll
                for (int nt = 0; nt < 4; nt++) {
                    const int r0 = wm0 + mt * 16 + g, c0 = wn0 + nt * 8 + 2 * t4;
                    dst[r0 * 132 + c0]           = acc[mt][nt][0];
                    dst[r0 * 132 + c0 + 1]       = acc[mt][nt][1];
                    dst[(r0 + 8) * 132 + c0]     = acc[mt][nt][2];
                    dst[(r0 + 8) * 132 + c0 + 1] = acc[mt][nt][3];
                }
        }
        __syncthreads();

        // pairwise: 16 groups x 64 pairs
        {
            const int grp = tid >> 4, s = tid & 15;
            const int i = s >> 1, jh = s & 1;
            float a4[4] = {0.f, 0.f, 0.f, 0.f};
#pragma unroll 8
            for (int h = 0; h < 128; h += 4) {
                const float4 av = *(const float4*)&sai[(grp * 8 + i) * 132 + h];
                const float4 cb = *(const float4*)&scb[h];
                const float4 wv = *(const float4*)&sw[h];
#pragma unroll
                for (int jj = 0; jj < 4; jj++) {
                    const int j = jh * 4 + jj;
                    const float4 bv = *(const float4*)&saj[(grp * 8 + j) * 132 + h];
                    a4[jj] = fmaf(fmaxf(av.x + bv.x + cb.x, 0.f), wv.x, a4[jj]);
                    a4[jj] = fmaf(fmaxf(av.y + bv.y + cb.y, 0.f), wv.y, a4[jj]);
                    a4[jj] = fmaf(fmaxf(av.z + bv.z + cb.z, 0.f), wv.z, a4[jj]);
                    a4[jj] = fmaf(fmaxf(av.w + bv.w + cb.w, 0.f), wv.w, a4[jj]);
                }
            }
#pragma unroll
            for (int jj = 0; jj < 4; jj++) {
                const int j = jh * 4 + jj;
                float c = 1.f / (1.f + expf(-(a4[jj] + cob0)));
                c *= salive[grp * 8 + j];
                if (i == j) c = 0.f;
                sC[grp * 64 + i * 8 + j] = c;
            }
        }
        __syncthreads();

        // context -> cat (tf32, stride 264) over U
        {
            const int colt = tid & 127, gh = tid >> 7;
#pragma unroll
            for (int gg = 0; gg < 8; gg++) {
                const int grp = gh * 8 + gg;
                const int rbase = br0 + grp * 8;
                float ev[8];
#pragma unroll
                for (int j = 0; j < 8; j++) ev[j] = e[(size_t)(rbase + j) * 128 + colt];
#pragma unroll
                for (int i = 0; i < 8; i++) {
                    float ctx = 0.f;
#pragma unroll
                    for (int j = 0; j < 8; j++)
                        ctx = fmaf(sC[grp * 64 + i * 8 + j], ev[j], ctx);
                    U[(grp * 8 + i) * 264 + colt]       = f2tf32(ev[i]);
                    U[(grp * 8 + i) * 264 + 128 + colt] = f2tf32(ctx);
                }
            }
        }

        // d1 = relu(cat @ Uh + b) -> U (stride 132)
        gemm_smemA(U, 264, 256, uhw, 128, Bs0, Bs1, acc, tid, wm0, wn0, g, t4);
        __syncthreads();   // all reads of cat done before overwrite
#pragma unroll
        for (int mt = 0; mt < 4; mt++)
#pragma unroll
            for (int nt = 0; nt < 4; nt++) {
                const int r0 = wm0 + mt * 16 + g, c0 = wn0 + nt * 8 + 2 * t4;
                const float b0 = uhb[c0], b1 = uhb[c0 + 1];
                U[r0 * 132 + c0]           = f2tf32(fmaxf(acc[mt][nt][0] + b0, 0.f));
                U[r0 * 132 + c0 + 1]       = f2tf32(fmaxf(acc[mt][nt][1] + b1, 0.f));
                U[(r0 + 8) * 132 + c0]     = f2tf32(fmaxf(acc[mt][nt][2] + b0, 0.f));
                U[(r0 + 8) * 132 + c0 + 1] = f2tf32(fmaxf(acc[mt][nt][3] + b1, 0.f));
            }

        // e = (e + relu(d1 @ Uo + b)) * alive
        gemm_smemA(U, 132, 128, uow, 128, Bs0, Bs1, acc, tid, wm0, wn0, g, t4);
#pragma unroll
        for (int mt = 0; mt < 4; mt++) {
            const int r0 = wm0 + mt * 16 + g;
            const float al0 = salive[r0];
            const float al1 = salive[r0 + 8];
#pragma unroll
            for (int nt = 0; nt < 4; nt++) {
                const int c0 = wn0 + nt * 8 + 2 * t4;
                const float b0 = uob[c0], b1 = uob[c0 + 1];
                float* p0 = e + (size_t)(br0 + r0) * 128 + c0;
                float* p1 = e + (size_t)(br0 + r0 + 8) * 128 + c0;
                const float2 e0 = *(const float2*)p0;
                const float2 e1 = *(const float2*)p1;
                float2 o0, o1;
                o0.x = (e0.x + fmaxf(acc[mt][nt][0] + b0, 0.f)) * al0;
                o0.y = (e0.y + fmaxf(acc[mt][nt][1] + b1, 0.f)) * al0;
                o1.x = (e1.x + fmaxf(acc[mt][nt][2] + b0, 0.f)) * al1;
                o1.y = (e1.y + fmaxf(acc[mt][nt][3] + b1, 0.f)) * al1;
                *(float2*)p0 = o0;
                *(float2*)p1 = o1;
            }
        }
        __syncthreads();   // e visible before next iteration / value head
    }

    // value head: v1 = relu(e @ W1 + b) -> U (stride 264)
    for (int p = 0; p < 2; p++) {
        gemm_gmemA(e + (size_t)br0 * 128, 128, 128, v1w + p * 128, 256,
                   As0, As1, Bs0, Bs1, acc, tid, wm0, wn0, g, t4);
#pragma unroll
        for (int mt = 0; mt < 4; mt++)
#pragma unroll
            for (int nt = 0; nt < 4; nt++) {
                const int r0 = wm0 + mt * 16 + g, c0 = wn0 + nt * 8 + 2 * t4;
                const int cg = p * 128 + c0;
                const float b0 = v1b[cg], b1 = v1b[cg + 1];
                U[r0 * 264 + cg]           = f2tf32(fmaxf(acc[mt][nt][0] + b0, 0.f));
                U[r0 * 264 + cg + 1]       = f2tf32(fmaxf(acc[mt][nt][1] + b1, 0.f));
                U[(r0 + 8) * 264 + cg]     = f2tf32(fmaxf(acc[mt][nt][2] + b0, 0.f));
                U[(r0 + 8) * 264 + cg + 1] = f2tf32(fmaxf(acc[mt][nt][3] + b1, 0.f));
            }
    }

    // v2 = relu(v1 @ W2 + b) folded into vow reduction
    float part[4][2];
#pragma unroll
    for (int mt = 0; mt < 4; mt++) { part[mt][0] = 0.f; part[mt][1] = 0.f; }
    for (int p = 0; p < 2; p++) {
        gemm_smemA(U, 264, 256, v2w + p * 128, 256, Bs0, Bs1, acc, tid, wm0, wn0, g, t4);
#pragma unroll
        for (int mt = 0; mt < 4; mt++)
#pragma unroll
            for (int nt = 0; nt < 4; nt++) {
                const int c0 = wn0 + nt * 8 + 2 * t4;
                const int cg = p * 128 + c0;
                const float b0 = v2b[cg], b1 = v2b[cg + 1];
                const float w0 = vow[cg], w1 = vow[cg + 1];
                part[mt][0] = fmaf(fmaxf(acc[mt][nt][0] + b0, 0.f), w0, part[mt][0]);
                part[mt][0] = fmaf(fmaxf(acc[mt][nt][1] + b1, 0.f), w1, part[mt][0]);
                part[mt][1] = fmaf(fmaxf(acc[mt][nt][2] + b0, 0.f), w0, part[mt][1]);
                part[mt][1] = fmaf(fmaxf(acc[mt][nt][3] + b1, 0.f), w1, part[mt][1]);
            }
    }
#pragma unroll
    for (int mt = 0; mt < 4; mt++)
#pragma unroll
        for (int h = 0; h < 2; h++) {
            part[mt][h] += __shfl_xor_sync(0xffffffffu, part[mt][h], 1);
            part[mt][h] += __shfl_xor_sync(0xffffffffu, part[mt][h], 2);
        }
    __syncthreads();
    if (t4 == 0) {
        const int wn = warp & 3;
#pragma unroll
        for (int mt = 0; mt < 4; mt++)
#pragma unroll
            for (int h = 0; h < 2; h++)
                sred[wn * 128 + wm0 + mt * 16 + g + h * 8] = part[mt][h];
    }
    __syncthreads();
    if (tid < 128) {
        values[br0 + tid] = sred[tid] + sred[128 + tid] + sred[256 + tid]
                          + sred[384 + tid] + __ldg(vob);
    }
}

// ================= launch =================
extern "C" void kernel_launch(void* const* d_in, const int* in_sizes, int n_in,
                              void* d_out, int out_size)
{
    const float* hidden = (const float*)d_in[0];
    const float* obs    = (const float*)d_in[1];
    const int*   dones  = (const int*)d_in[2];
    const float* e1w = (const float*)d_in[3];
    const float* e1b = (const float*)d_in[4];
    const float* e2w = (const float*)d_in[5];
    const float* e2b = (const float*)d_in[6];
    const float* Wi  = (const float*)d_in[7];
    const float* bi  = (const float*)d_in[8];
    const float* Wh  = (const float*)d_in[9];
    const float* bhn = (const float*)d_in[10];
    const float* chw = (const float*)d_in[11];
    const float* chb = (const float*)d_in[12];
    const float* cow = (const float*)d_in[13];
    const float* cob = (const float*)d_in[14];
    const float* uhw = (const float*)d_in[15];
    const float* uhb = (const float*)d_in[16];
    const float* uow = (const float*)d_in[17];
    const float* uob = (const float*)d_in[18];
    const float* v1w = (const float*)d_in[19];
    const float* v1b = (const float*)d_in[20];
    const float* v2w = (const float*)d_in[21];
    const float* v2b = (const float*)d_in[22];
    const float* vow = (const float*)d_in[23];
    const float* vob = (const float*)d_in[24];
    float* out = (float*)d_out;

    float *gi, *e;
    cudaGetSymbolAddress((void**)&gi, g_gi);
    cudaGetSymbolAddress((void**)&e,  g_e);

    const int smE = (2 * 128 * 36 + 2 * 32 * 136 + 128 * 132) * 4;
    const int smM = (2 * 128 * 36 + 2 * 32 * 136 + 128 * 264
                     + 1024 + 128 + 128 + 128 + 512) * 4;
    cudaFuncSetAttribute(embed_gi_fused, cudaFuncAttributeMaxDynamicSharedMemorySize, smE);
    cudaFuncSetAttribute(post_gru_mega,  cudaFuncAttributeMaxDynamicSharedMemorySize, smM);

    embed_gi_fused<<<512, 256, smE>>>(obs, e1w, e1b, e2w, e2b, Wi, bi, gi);
    gru_kernel<<<128, 384>>>(gi, dones, Wh, bhn, hidden, e, out);
    post_gru_mega<<<512, 256, smM>>>(e, dones, chw, chb, cow, cob,
                                     uhw, uhb, uow, uob,
                                     v1w, v1b, v2w, v2b, vow, vob, out + 65536);
}